// round 5
// baseline (speedup 1.0000x reference)
#include <cuda_runtime.h>
#include <cuda_bf16.h>
#include <cstdint>
#include <math.h>

#define T_TOK 4096
#define BATCH 2
#define SEQ   2048
#define NHEAD 32
#define HDIM  64
#define HID   2048
#define QKV_N 2176
#define ROPE_HALF 32

// ---------------- scratch (device globals; no allocation allowed) ----------
__device__ float g_qkv   [T_TOK * QKV_N];
__device__ float g_q     [T_TOK * HID];    // tf32-rounded
__device__ float g_k     [T_TOK * HDIM];   // tf32-rounded
__device__ float g_v     [T_TOK * HDIM];   // tf32-rounded
__device__ float g_attn  [T_TOK * HID];    // tf32-rounded
__device__ float g_hs    [T_TOK * HID];    // tf32-rounded inputs
__device__ float g_wqkv  [QKV_N * HID];
__device__ float g_wdense[HID * HID];

// ---------------- helpers ---------------------------------------------------
__device__ __forceinline__ uint32_t f2tf(float x) {
    uint32_t r;
    asm("cvt.rna.tf32.f32 %0, %1;" : "=r"(r) : "f"(x));
    return r;
}

__device__ __forceinline__ void mma_tf32(float* c,
    uint32_t a0, uint32_t a1, uint32_t a2, uint32_t a3,
    uint32_t b0, uint32_t b1)
{
    asm volatile(
        "mma.sync.aligned.m16n8k8.row.col.f32.tf32.tf32.f32 "
        "{%0,%1,%2,%3}, {%4,%5,%6,%7}, {%8,%9}, {%0,%1,%2,%3};"
        : "+f"(c[0]), "+f"(c[1]), "+f"(c[2]), "+f"(c[3])
        : "r"(a0), "r"(a1), "r"(a2), "r"(a3), "r"(b0), "r"(b1));
}

__device__ __forceinline__ void cp_async16(uint32_t dst, const void* src) {
    asm volatile("cp.async.cg.shared.global [%0], [%1], 16;" :: "r"(dst), "l"(src));
}

// ---------------------------------------------------------------------------
// tf32 pre-rounding pass
// ---------------------------------------------------------------------------
__global__ __launch_bounds__(256) void tf32_round_kernel(
    const float* __restrict__ src, float* __restrict__ dst, int n4)
{
    int i = blockIdx.x * blockDim.x + threadIdx.x;
    if (i < n4) {
        float4 v = ((const float4*)src)[i];
        uint4 u;
        u.x = f2tf(v.x); u.y = f2tf(v.y); u.z = f2tf(v.z); u.w = f2tf(v.w);
        ((uint4*)dst)[i] = u;
    }
}

// ---------------------------------------------------------------------------
// TF32 GEMM (NT), 3-stage cp.async pipeline.
// BM=BN=128, BK=32, 256 threads (2x4 warps), 2 CTAs/SM.
// ---------------------------------------------------------------------------
#define GST (128 * 36)                 // one matrix stage, floats
#define GEMM_SMEM (3 * 2 * GST * 4)    // 110592 B

__global__ __launch_bounds__(256, 2) void gemm_tf32_nt(
    const float* __restrict__ A, const float* __restrict__ B,
    float* __restrict__ C, int M, int N, int K)
{
    extern __shared__ float sm[];
    float* As = sm;                  // 3 stages x [128][36]
    float* Bs = sm + 3 * GST;

    const int tid  = threadIdx.x;
    const int lane = tid & 31, warp = tid >> 5;
    const int g  = lane >> 2, tg = lane & 3;
    const int wm = warp >> 2, wn = warp & 3;
    const int bm = blockIdx.y * 128, bn = blockIdx.x * 128;

    const uint32_t as_base = (uint32_t)__cvta_generic_to_shared(As);
    const uint32_t bs_base = (uint32_t)__cvta_generic_to_shared(Bs);

    auto prefetch = [&](int stage, int k0) {
        #pragma unroll
        for (int l = 0; l < 4; l++) {
            int idx = l * 256 + tid;
            int row = idx >> 3, c4 = (idx & 7) * 4;
            cp_async16(as_base + (uint32_t)(stage * GST + row * 36 + c4) * 4,
                       A + (size_t)(bm + row) * K + k0 + c4);
            cp_async16(bs_base + (uint32_t)(stage * GST + row * 36 + c4) * 4,
                       B + (size_t)(bn + row) * K + k0 + c4);
        }
        asm volatile("cp.async.commit_group;");
    };

    float acc[4][4][4];
    #pragma unroll
    for (int i = 0; i < 4; i++)
        #pragma unroll
        for (int j = 0; j < 4; j++)
            #pragma unroll
            for (int r = 0; r < 4; r++) acc[i][j][r] = 0.f;

    const int nK = K / 32;
    prefetch(0, 0);
    prefetch(1, 32);

    int stage = 0;
    for (int kt = 0; kt < nK; kt++) {
        __syncthreads();   // all warps done reading the stage about to be refilled
        if (kt + 2 < nK) {
            prefetch((stage + 2) % 3, (kt + 2) * 32);
            asm volatile("cp.async.wait_group 2;");
        } else if (kt + 2 == nK) {
            asm volatile("cp.async.wait_group 1;");
        } else {
            asm volatile("cp.async.wait_group 0;");
        }
        __syncthreads();   // stage `stage` visible to all warps

        const float* as = As + stage * GST;
        const float* bs = Bs + stage * GST;

        #pragma unroll
        for (int kk = 0; kk < 4; kk++) {
            uint32_t af[4][4], bf[4][2];
            const int c = kk * 8;
            #pragma unroll
            for (int mi = 0; mi < 4; mi++) {
                int r = wm * 64 + mi * 16;
                af[mi][0] = __float_as_uint(as[(r + g    ) * 36 + c + tg    ]);
                af[mi][1] = __float_as_uint(as[(r + g + 8) * 36 + c + tg    ]);
                af[mi][2] = __float_as_uint(as[(r + g    ) * 36 + c + tg + 4]);
                af[mi][3] = __float_as_uint(as[(r + g + 8) * 36 + c + tg + 4]);
            }
            #pragma unroll
            for (int ni = 0; ni < 4; ni++) {
                int r = wn * 32 + ni * 8;
                bf[ni][0] = __float_as_uint(bs[(r + g) * 36 + c + tg    ]);
                bf[ni][1] = __float_as_uint(bs[(r + g) * 36 + c + tg + 4]);
            }
            #pragma unroll
            for (int mi = 0; mi < 4; mi++)
                #pragma unroll
                for (int ni = 0; ni < 4; ni++)
                    mma_tf32(acc[mi][ni], af[mi][0], af[mi][1], af[mi][2], af[mi][3],
                             bf[ni][0], bf[ni][1]);
        }
        stage = (stage + 1) % 3;
    }

    #pragma unroll
    for (int mi = 0; mi < 4; mi++) {
        size_t r0 = (size_t)(bm + wm * 64 + mi * 16 + g);
        #pragma unroll
        for (int ni = 0; ni < 4; ni++) {
            int c = bn + wn * 32 + ni * 8 + tg * 2;
            *(float2*)(C + r0 * N + c)       = make_float2(acc[mi][ni][0], acc[mi][ni][1]);
            *(float2*)(C + (r0 + 8) * N + c) = make_float2(acc[mi][ni][2], acc[mi][ni][3]);
        }
    }
}

// ---------------------------------------------------------------------------
// RoPE + split. Emits tf32-rounded q, k, v.
// ---------------------------------------------------------------------------
__global__ __launch_bounds__(256) void rope_split_kernel(
    const float* __restrict__ qkv,
    const float* __restrict__ cosb, const float* __restrict__ sinb,
    float* __restrict__ q, float* __restrict__ k, float* __restrict__ v)
{
    const int t = blockIdx.x;
    const float* row = qkv + (size_t)t * QKV_N;
    const float* cs  = cosb + t * ROPE_HALF;
    const float* sn  = sinb + t * ROPE_HALF;

    for (int i = threadIdx.x; i < NHEAD * ROPE_HALF; i += blockDim.x) {
        int hh = i >> 5, d = i & 31;
        float c = cs[d], s = sn[d];
        float x1 = row[hh * HDIM + d];
        float x2 = row[hh * HDIM + d + ROPE_HALF];
        ((uint32_t*)q)[(size_t)t * HID + hh * HDIM + d]             = f2tf(x1 * c - x2 * s);
        ((uint32_t*)q)[(size_t)t * HID + hh * HDIM + d + ROPE_HALF] = f2tf(x2 * c + x1 * s);
    }
    for (int i = threadIdx.x; i < ROPE_HALF; i += blockDim.x) {
        float c = cs[i], s = sn[i];
        float x1 = row[HID + i];
        float x2 = row[HID + i + ROPE_HALF];
        ((uint32_t*)k)[(size_t)t * HDIM + i]             = f2tf(x1 * c - x2 * s);
        ((uint32_t*)k)[(size_t)t * HDIM + i + ROPE_HALF] = f2tf(x2 * c + x1 * s);
    }
    for (int i = threadIdx.x; i < HDIM; i += blockDim.x) {
        ((uint32_t*)v)[(size_t)t * HDIM + i] = f2tf(row[HID + HDIM + i]);
    }
}

// ---------------------------------------------------------------------------
// Causal flash attention v3: BM=128 (8 warps), BN=64, double-buffered KV,
// shuffle-based P re-fragmentation (no smem round-trip for P).
// ---------------------------------------------------------------------------
#define KV_T   (64 * 68)
#define FA_SMEM ((4 * KV_T + 128 * 68) * 4)

__global__ __launch_bounds__(256, 2) void flash_tf32_v3(
    const float* __restrict__ Q, const float* __restrict__ Kg,
    const float* __restrict__ Vg, float* __restrict__ O)
{
    extern __shared__ float sm[];
    float* QP = sm + 4 * KV_T;

    const int tid  = threadIdx.x;
    const int lane = tid & 31, warp = tid >> 5;
    const int g = lane >> 2, tg = lane & 3;
    const int qt = blockIdx.x, h = blockIdx.y, b = blockIdx.z;
    const float scale = 0.125f;
    const int nkt = 2 * qt + 2;
    const int row_min = qt * 128 + warp * 16;
    const bool odd = tg & 1;
    const int srcA = (lane & 28) + (tg >> 1);  // g*4 + tg/2
    const int srcB = srcA + 2;

    const uint32_t sm_base = (uint32_t)__cvta_generic_to_shared(sm);
    const uint32_t qp_base = sm_base + 4 * KV_T * 4;

    // Q tile -> QP (group 0)
    for (int i = tid * 4; i < 128 * 64; i += 1024) {
        int r = i >> 6, c = i & 63;
        cp_async16(qp_base + (uint32_t)(r * 68 + c) * 4,
                   Q + ((size_t)(b * SEQ + qt * 128 + r) * NHEAD + h) * HDIM + c);
    }
    asm volatile("cp.async.commit_group;");

    auto prefetch_kv = [&](int s, int kt) {
        const float* kp = Kg + (size_t)(b * SEQ + kt * 64) * HDIM;
        const float* vp = Vg + (size_t)(b * SEQ + kt * 64) * HDIM;
        #pragma unroll
        for (int i = tid * 4; i < 64 * 64; i += 1024) {
            int r = i >> 6, c = i & 63;
            cp_async16(sm_base + (uint32_t)(s * KV_T + r * 68 + c) * 4, kp + r * 64 + c);
            cp_async16(sm_base + (uint32_t)((2 + s) * KV_T + r * 68 + c) * 4, vp + r * 64 + c);
        }
        asm volatile("cp.async.commit_group;");
    };

    prefetch_kv(0, 0);
    prefetch_kv(1, 1);

    asm volatile("cp.async.wait_group 2;");   // Q arrived
    __syncthreads();

    uint32_t qf[8][4];
    {
        const float* qs = QP + warp * 16 * 68;
        #pragma unroll
        for (int kk = 0; kk < 8; kk++) {
            qf[kk][0] = __float_as_uint(qs[(g    ) * 68 + kk * 8 + tg    ]);
            qf[kk][1] = __float_as_uint(qs[(g + 8) * 68 + kk * 8 + tg    ]);
            qf[kk][2] = __float_as_uint(qs[(g    ) * 68 + kk * 8 + tg + 4]);
            qf[kk][3] = __float_as_uint(qs[(g + 8) * 68 + kk * 8 + tg + 4]);
        }
    }

    float oacc[8][4];
    #pragma unroll
    for (int d = 0; d < 8; d++)
        #pragma unroll
        for (int r = 0; r < 4; r++) oacc[d][r] = 0.f;
    float mrow[2] = {-1e30f, -1e30f};
    float lrow[2] = {0.f, 0.f};

    for (int kt = 0; kt < nkt; kt++) {
        const int s = kt & 1;
        if (kt + 1 < nkt) asm volatile("cp.async.wait_group 1;");
        else              asm volatile("cp.async.wait_group 0;");
        __syncthreads();

        const bool skip = (kt * 64) > (row_min + 15);
        if (!skip) {
            const float* ks = sm + s * KV_T;
            const float* vs = sm + (2 + s) * KV_T;

            // S = Q K^T
            float sacc[8][4];
            #pragma unroll
            for (int ni = 0; ni < 8; ni++)
                #pragma unroll
                for (int r = 0; r < 4; r++) sacc[ni][r] = 0.f;

            #pragma unroll
            for (int kk = 0; kk < 8; kk++) {
                #pragma unroll
                for (int ni = 0; ni < 8; ni++) {
                    uint32_t b0 = __float_as_uint(ks[(ni * 8 + g) * 68 + kk * 8 + tg    ]);
                    uint32_t b1 = __float_as_uint(ks[(ni * 8 + g) * 68 + kk * 8 + tg + 4]);
                    mma_tf32(sacc[ni], qf[kk][0], qf[kk][1], qf[kk][2], qf[kk][3], b0, b1);
                }
            }

            const bool need_mask = (kt * 64 + 63) > row_min;
            const int rloc[2] = {row_min + g, row_min + g + 8};

            #pragma unroll
            for (int rr = 0; rr < 2; rr++) {
                float mx = -1e30f;
                #pragma unroll
                for (int ni = 0; ni < 8; ni++) {
                    float v0 = sacc[ni][rr * 2 + 0] * scale;
                    float v1 = sacc[ni][rr * 2 + 1] * scale;
                    if (need_mask) {
                        int c0 = kt * 64 + ni * 8 + tg * 2;
                        if (c0     > rloc[rr]) v0 = -1e30f;
                        if (c0 + 1 > rloc[rr]) v1 = -1e30f;
                    }
                    sacc[ni][rr * 2 + 0] = v0;
                    sacc[ni][rr * 2 + 1] = v1;
                    mx = fmaxf(mx, fmaxf(v0, v1));
                }
                mx = fmaxf(mx, __shfl_xor_sync(0xffffffffu, mx, 1));
                mx = fmaxf(mx, __shfl_xor_sync(0xffffffffu, mx, 2));
                float mnew = fmaxf(mrow[rr], mx);
                float corr = __expf(mrow[rr] - mnew);
                float sum = 0.f;
                #pragma unroll
                for (int ni = 0; ni < 8; ni++) {
                    float e0 = __expf(sacc[ni][rr * 2 + 0] - mnew);
                    float e1 = __expf(sacc[ni][rr * 2 + 1] - mnew);
                    sacc[ni][rr * 2 + 0] = e0;
                    sacc[ni][rr * 2 + 1] = e1;
                    sum += e0 + e1;
                }
                sum += __shfl_xor_sync(0xffffffffu, sum, 1);
                sum += __shfl_xor_sync(0xffffffffu, sum, 2);
                lrow[rr] = lrow[rr] * corr + sum;
                mrow[rr] = mnew;
                #pragma unroll
                for (int di = 0; di < 8; di++) {
                    oacc[di][rr * 2 + 0] *= corr;
                    oacc[di][rr * 2 + 1] *= corr;
                }
            }

            // round P to tf32 in-place (same rounding point as R4)
            #pragma unroll
            for (int ni = 0; ni < 8; ni++)
                #pragma unroll
                for (int r = 0; r < 4; r++)
                    sacc[ni][r] = __uint_as_float(f2tf(sacc[ni][r]));

            // O += P @ V, P re-fragmented via shuffles:
            // A[g][kk*8+tg] lives in sacc[kk][tg&1 (+2 for row g+8)] of lane g*4+(tg>>1)
            #pragma unroll
            for (int kk = 0; kk < 8; kk++) {
                float vA0 = __shfl_sync(0xffffffffu, sacc[kk][0], srcA);
                float vA1 = __shfl_sync(0xffffffffu, sacc[kk][1], srcA);
                float vA2 = __shfl_sync(0xffffffffu, sacc[kk][2], srcA);
                float vA3 = __shfl_sync(0xffffffffu, sacc[kk][3], srcA);
                float vB0 = __shfl_sync(0xffffffffu, sacc[kk][0], srcB);
                float vB1 = __shfl_sync(0xffffffffu, sacc[kk][1], srcB);
                float vB2 = __shfl_sync(0xffffffffu, sacc[kk][2], srcB);
                float vB3 = __shfl_sync(0xffffffffu, sacc[kk][3], srcB);
                uint32_t a0 = __float_as_uint(odd ? vA1 : vA0);
                uint32_t a1 = __float_as_uint(odd ? vA3 : vA2);
                uint32_t a2 = __float_as_uint(odd ? vB1 : vB0);
                uint32_t a3 = __float_as_uint(odd ? vB3 : vB2);
                #pragma unroll
                for (int di = 0; di < 8; di++) {
                    uint32_t b0 = __float_as_uint(vs[(kk * 8 + tg    ) * 68 + di * 8 + g]);
                    uint32_t b1 = __float_as_uint(vs[(kk * 8 + tg + 4) * 68 + di * 8 + g]);
                    mma_tf32(oacc[di], a0, a1, a2, a3, b0, b1);
                }
            }
        }

        __syncthreads();   // all reads of stage s done before refill
        if (kt + 2 < nkt) prefetch_kv(s, kt + 2);
    }

    // write O (tf32-rounded: A operand of the dense GEMM)
    float inv0 = 1.f / lrow[0], inv1 = 1.f / lrow[1];
    size_t row0 = (size_t)(b * SEQ + qt * 128 + warp * 16 + g);
    size_t row1 = row0 + 8;
    #pragma unroll
    for (int di = 0; di < 8; di++) {
        int c = h * 64 + di * 8 + tg * 2;
        uint32_t o0 = f2tf(oacc[di][0] * inv0), o1 = f2tf(oacc[di][1] * inv0);
        uint32_t o2 = f2tf(oacc[di][2] * inv1), o3 = f2tf(oacc[di][3] * inv1);
        *(float2*)(O + row0 * HID + c) = make_float2(__uint_as_float(o0), __uint_as_float(o1));
        *(float2*)(O + row1 * HID + c) = make_float2(__uint_as_float(o2), __uint_as_float(o3));
    }
}

// ---------------------------------------------------------------------------
extern "C" void kernel_launch(void* const* d_in, const int* in_sizes, int n_in,
                              void* d_out, int out_size)
{
    const float* hs     = (const float*)d_in[0];
    const float* cosb   = (const float*)d_in[1];
    const float* sinb   = (const float*)d_in[2];
    const float* wqkv   = (const float*)d_in[3];
    const float* wdense = (const float*)d_in[4];
    float* out = (float*)d_out;

    float *p_qkv, *p_q, *p_k, *p_v, *p_attn, *p_hs, *p_wqkv, *p_wdense;
    cudaGetSymbolAddress((void**)&p_qkv,    g_qkv);
    cudaGetSymbolAddress((void**)&p_q,      g_q);
    cudaGetSymbolAddress((void**)&p_k,      g_k);
    cudaGetSymbolAddress((void**)&p_v,      g_v);
    cudaGetSymbolAddress((void**)&p_attn,   g_attn);
    cudaGetSymbolAddress((void**)&p_hs,     g_hs);
    cudaGetSymbolAddress((void**)&p_wqkv,   g_wqkv);
    cudaGetSymbolAddress((void**)&p_wdense, g_wdense);

    cudaFuncSetAttribute(gemm_tf32_nt,
                         cudaFuncAttributeMaxDynamicSharedMemorySize, GEMM_SMEM);
    cudaFuncSetAttribute(flash_tf32_v3,
                         cudaFuncAttributeMaxDynamicSharedMemorySize, FA_SMEM);

    // 0) pre-round inputs to tf32
    tf32_round_kernel<<<(T_TOK * HID / 4 + 255) / 256, 256>>>(hs, p_hs, T_TOK * HID / 4);
    tf32_round_kernel<<<(QKV_N * HID / 4 + 255) / 256, 256>>>(wqkv, p_wqkv, QKV_N * HID / 4);
    tf32_round_kernel<<<(HID * HID / 4 + 255) / 256, 256>>>(wdense, p_wdense, HID * HID / 4);

    // 1) QKV projection
    {
        dim3 grid(QKV_N / 128, T_TOK / 128);
        gemm_tf32_nt<<<grid, 256, GEMM_SMEM>>>(p_hs, p_wqkv, p_qkv, T_TOK, QKV_N, HID);
    }
    // 2) RoPE + split
    rope_split_kernel<<<T_TOK, 256>>>(p_qkv, cosb, sinb, p_q, p_k, p_v);

    // 3) causal flash attention
    {
        dim3 grid(SEQ / 128, NHEAD, BATCH);
        flash_tf32_v3<<<grid, 256, FA_SMEM>>>(p_q, p_k, p_v, p_attn);
    }
    // 4) dense projection
    {
        dim3 grid(HID / 128, T_TOK / 128);
        gemm_tf32_nt<<<grid, 256, GEMM_SMEM>>>(p_attn, p_wdense, out, T_TOK, HID, HID);
    }
}

// round 7
// speedup vs baseline: 2.1009x; 2.1009x over previous
#include <cuda_runtime.h>
#include <cuda_fp16.h>
#include <cstdint>
#include <math.h>

#define T_TOK 4096
#define BATCH 2
#define SEQ   2048
#define NHEAD 32
#define HDIM  64
#define HID   2048
#define QKV_N 2176
#define ROPE_HALF 32

// ---------------- scratch (device globals; no allocation allowed) ----------
__device__ float  g_qkv   [T_TOK * QKV_N];          // qkv projection output (fp32)
__device__ __half g_hs_h  [T_TOK * HID];            // fp16 inputs
__device__ __half g_wqkv_h[QKV_N * HID];
__device__ __half g_wd_h  [HID * HID];
__device__ __half g_q_h   [T_TOK * HID];            // roped q * 0.125, fp16
__device__ __half g_k_h   [T_TOK * HDIM];           // roped k, fp16
__device__ __half g_vt_h  [BATCH * HDIM * SEQ];     // V transposed: [b][d][s], fp16
__device__ __half g_attn_h[T_TOK * HID];            // attention out, fp16

// ---------------- helpers ---------------------------------------------------
__device__ __forceinline__ void mma_f16(float* c,
    uint32_t a0, uint32_t a1, uint32_t a2, uint32_t a3,
    uint32_t b0, uint32_t b1)
{
    asm volatile(
        "mma.sync.aligned.m16n8k16.row.col.f32.f16.f16.f32 "
        "{%0,%1,%2,%3}, {%4,%5,%6,%7}, {%8,%9}, {%0,%1,%2,%3};"
        : "+f"(c[0]), "+f"(c[1]), "+f"(c[2]), "+f"(c[3])
        : "r"(a0), "r"(a1), "r"(a2), "r"(a3), "r"(b0), "r"(b1));
}

__device__ __forceinline__ void cp_async16(uint32_t dst, const void* src) {
    asm volatile("cp.async.cg.shared.global [%0], [%1], 16;" :: "r"(dst), "l"(src));
}

__device__ __forceinline__ uint32_t pack_h2(float lo, float hi) {
    __half2 h = __floats2half2_rn(lo, hi);
    return *(uint32_t*)&h;
}

__device__ __forceinline__ uint32_t ldh2(const __half* p) {
    return *(const uint32_t*)p;
}

// ---------------------------------------------------------------------------
// fp32 -> fp16 conversion pass (bandwidth bound)
// ---------------------------------------------------------------------------
__global__ __launch_bounds__(256) void f32_to_f16_kernel(
    const float* __restrict__ src, __half* __restrict__ dst, int n4)
{
    int i = blockIdx.x * blockDim.x + threadIdx.x;
    if (i < n4) {
        float4 v = ((const float4*)src)[i];
        uint2 u;
        u.x = pack_h2(v.x, v.y);
        u.y = pack_h2(v.z, v.w);
        ((uint2*)dst)[i] = u;
    }
}

// ---------------------------------------------------------------------------
// FP16 GEMM (NT): C[m][n] = sum_k A[m][k]*B[n][k], fp32 accumulate.
// BM=BN=128, BK=64, 256 threads (2x4 warps), 2-stage cp.async, 2 CTAs/SM.
// smem rows padded to 72 halves -> conflict-free half2 fragment loads.
// ---------------------------------------------------------------------------
#define GSTH (128 * 72)                 // halves per matrix stage
#define GEMM_SMEM (2 * 2 * GSTH * 2)    // 73728 B

__global__ __launch_bounds__(256, 2) void gemm_f16_nt(
    const __half* __restrict__ A, const __half* __restrict__ B,
    float* __restrict__ C, int M, int N, int K)
{
    extern __shared__ __half smh[];
    __half* As = smh;                 // 2 stages x [128][72]
    __half* Bs = smh + 2 * GSTH;

    const int tid  = threadIdx.x;
    const int lane = tid & 31, warp = tid >> 5;
    const int g  = lane >> 2, tg = lane & 3;
    const int wm = warp >> 2, wn = warp & 3;
    const int bm = blockIdx.y * 128, bn = blockIdx.x * 128;

    const uint32_t as_base = (uint32_t)__cvta_generic_to_shared(As);
    const uint32_t bs_base = (uint32_t)__cvta_generic_to_shared(Bs);

    auto prefetch = [&](int stage, int k0) {
        #pragma unroll
        for (int l = 0; l < 4; l++) {
            int idx = l * 256 + tid;
            int row = idx >> 3, ch = (idx & 7) * 8;     // 8 halves = 16B per chunk
            cp_async16(as_base + (uint32_t)(stage * GSTH + row * 72 + ch) * 2,
                       A + (size_t)(bm + row) * K + k0 + ch);
            cp_async16(bs_base + (uint32_t)(stage * GSTH + row * 72 + ch) * 2,
                       B + (size_t)(bn + row) * K + k0 + ch);
        }
        asm volatile("cp.async.commit_group;");
    };

    float acc[4][4][4];
    #pragma unroll
    for (int i = 0; i < 4; i++)
        #pragma unroll
        for (int j = 0; j < 4; j++)
            #pragma unroll
            for (int r = 0; r < 4; r++) acc[i][j][r] = 0.f;

    const int nK = K / 64;
    prefetch(0, 0);

    for (int kt = 0; kt < nK; kt++) {
        int s = kt & 1;
        if (kt + 1 < nK) {
            prefetch(s ^ 1, (kt + 1) * 64);
            asm volatile("cp.async.wait_group 1;");
        } else {
            asm volatile("cp.async.wait_group 0;");
        }
        __syncthreads();

        const __half* as = As + s * GSTH;
        const __half* bs = Bs + s * GSTH;

        #pragma unroll
        for (int kk = 0; kk < 4; kk++) {
            uint32_t af[4][4], bf[4][2];
            const int c = kk * 16;
            #pragma unroll
            for (int mi = 0; mi < 4; mi++) {
                int r = wm * 64 + mi * 16;
                af[mi][0] = ldh2(as + (r + g    ) * 72 + c + 2 * tg);
                af[mi][1] = ldh2(as + (r + g + 8) * 72 + c + 2 * tg);
                af[mi][2] = ldh2(as + (r + g    ) * 72 + c + 8 + 2 * tg);
                af[mi][3] = ldh2(as + (r + g + 8) * 72 + c + 8 + 2 * tg);
            }
            #pragma unroll
            for (int ni = 0; ni < 4; ni++) {
                int r = wn * 32 + ni * 8;
                bf[ni][0] = ldh2(bs + (r + g) * 72 + c + 2 * tg);
                bf[ni][1] = ldh2(bs + (r + g) * 72 + c + 8 + 2 * tg);
            }
            #pragma unroll
            for (int mi = 0; mi < 4; mi++)
                #pragma unroll
                for (int ni = 0; ni < 4; ni++)
                    mma_f16(acc[mi][ni], af[mi][0], af[mi][1], af[mi][2], af[mi][3],
                            bf[ni][0], bf[ni][1]);
        }
        __syncthreads();
    }

    #pragma unroll
    for (int mi = 0; mi < 4; mi++) {
        size_t r0 = (size_t)(bm + wm * 64 + mi * 16 + g);
        #pragma unroll
        for (int ni = 0; ni < 4; ni++) {
            int c = bn + wn * 32 + ni * 8 + tg * 2;
            *(float2*)(C + r0 * N + c)       = make_float2(acc[mi][ni][0], acc[mi][ni][1]);
            *(float2*)(C + (r0 + 8) * N + c) = make_float2(acc[mi][ni][2], acc[mi][ni][3]);
        }
    }
}

// ---------------------------------------------------------------------------
// RoPE + split. Emits fp16: q (pre-scaled by 0.125), k, and V transposed.
// ---------------------------------------------------------------------------
__global__ __launch_bounds__(256) void rope_split_kernel(
    const float* __restrict__ qkv,
    const float* __restrict__ cosb, const float* __restrict__ sinb,
    __half* __restrict__ q, __half* __restrict__ k, __half* __restrict__ vt)
{
    const int t = blockIdx.x;
    const int bb = t >> 11;          // t / SEQ
    const int ss = t & (SEQ - 1);
    const float* row = qkv + (size_t)t * QKV_N;
    const float* cs  = cosb + t * ROPE_HALF;
    const float* sn  = sinb + t * ROPE_HALF;

    for (int i = threadIdx.x; i < NHEAD * ROPE_HALF; i += blockDim.x) {
        int hh = i >> 5, d = i & 31;
        float c = cs[d], s = sn[d];
        float x1 = row[hh * HDIM + d];
        float x2 = row[hh * HDIM + d + ROPE_HALF];
        q[(size_t)t * HID + hh * HDIM + d]             = __float2half_rn((x1 * c - x2 * s) * 0.125f);
        q[(size_t)t * HID + hh * HDIM + d + ROPE_HALF] = __float2half_rn((x2 * c + x1 * s) * 0.125f);
    }
    for (int i = threadIdx.x; i < ROPE_HALF; i += blockDim.x) {
        float c = cs[i], s = sn[i];
        float x1 = row[HID + i];
        float x2 = row[HID + i + ROPE_HALF];
        k[(size_t)t * HDIM + i]             = __float2half_rn(x1 * c - x2 * s);
        k[(size_t)t * HDIM + i + ROPE_HALF] = __float2half_rn(x2 * c + x1 * s);
    }
    for (int i = threadIdx.x; i < HDIM; i += blockDim.x) {
        vt[((size_t)(bb * HDIM + i)) * SEQ + ss] = __float2half_rn(row[HID + HDIM + i]);
    }
}

// ---------------------------------------------------------------------------
// Causal flash attention, fp16 mma. BM=128 (8 warps), BN=64, double-buffered
// K/Vt via cp.async, P stays in registers (S C-frag == PV A-frag for f16).
// smem (halves): Ks[2][64][72], Vs[2][64][72], Qs[128][72].
// ---------------------------------------------------------------------------
#define KST (64 * 72)
#define FA_SMEM ((4 * KST + 128 * 72) * 2)   // 55296 B

__global__ __launch_bounds__(256, 2) void flash_f16(
    const __half* __restrict__ Q, const __half* __restrict__ Kg,
    const __half* __restrict__ Vt, __half* __restrict__ O)
{
    extern __shared__ __half smh[];
    __half* QP = smh + 4 * KST;

    const int tid  = threadIdx.x;
    const int lane = tid & 31, warp = tid >> 5;
    const int g = lane >> 2, tg = lane & 3;
    const int qt = blockIdx.x, h = blockIdx.y, b = blockIdx.z;
    const int nkt = 2 * qt + 2;
    const int row_min = qt * 128 + warp * 16;

    const uint32_t sm_base = (uint32_t)__cvta_generic_to_shared(smh);
    const uint32_t qp_base = sm_base + 4 * KST * 2;

    // Q tile -> QP (group 0): 128 rows x 8 chunks
    for (int i = tid; i < 1024; i += 256) {
        int r = i >> 3, ch = (i & 7) * 8;
        cp_async16(qp_base + (uint32_t)(r * 72 + ch) * 2,
                   Q + ((size_t)(b * SEQ + qt * 128 + r) * NHEAD + h) * HDIM + ch);
    }
    asm volatile("cp.async.commit_group;");

    auto prefetch_kv = [&](int s, int kt) {
        #pragma unroll
        for (int i = tid; i < 512; i += 256) {
            int r = i >> 3, ch = (i & 7) * 8;
            cp_async16(sm_base + (uint32_t)(s * KST + r * 72 + ch) * 2,
                       Kg + (size_t)(b * SEQ + kt * 64 + r) * HDIM + ch);
            cp_async16(sm_base + (uint32_t)((2 + s) * KST + r * 72 + ch) * 2,
                       Vt + ((size_t)(b * HDIM + r)) * SEQ + kt * 64 + ch);
        }
        asm volatile("cp.async.commit_group;");
    };

    prefetch_kv(0, 0);
    prefetch_kv(1, 1);

    asm volatile("cp.async.wait_group 2;");   // Q arrived
    __syncthreads();

    // Q fragments (invariant across KV tiles): 4 k-steps of 16
    uint32_t qf[4][4];
    {
        const __half* qs = QP + warp * 16 * 72;
        #pragma unroll
        for (int kk = 0; kk < 4; kk++) {
            const int c = kk * 16;
            qf[kk][0] = ldh2(qs + (g    ) * 72 + c + 2 * tg);
            qf[kk][1] = ldh2(qs + (g + 8) * 72 + c + 2 * tg);
            qf[kk][2] = ldh2(qs + (g    ) * 72 + c + 8 + 2 * tg);
            qf[kk][3] = ldh2(qs + (g + 8) * 72 + c + 8 + 2 * tg);
        }
    }

    float oacc[8][4];
    #pragma unroll
    for (int d = 0; d < 8; d++)
        #pragma unroll
        for (int r = 0; r < 4; r++) oacc[d][r] = 0.f;
    float mrow[2] = {-1e30f, -1e30f};
    float lrow[2] = {0.f, 0.f};

    for (int kt = 0; kt < nkt; kt++) {
        const int s = kt & 1;
        if (kt + 1 < nkt) asm volatile("cp.async.wait_group 1;");
        else              asm volatile("cp.async.wait_group 0;");
        __syncthreads();

        const bool skip = (kt * 64) > (row_min + 15);
        if (!skip) {
            const __half* ks = smh + s * KST;
            const __half* vs = smh + (2 + s) * KST;

            // S = (Q*0.125) K^T
            float sacc[8][4];
            #pragma unroll
            for (int ni = 0; ni < 8; ni++)
                #pragma unroll
                for (int r = 0; r < 4; r++) sacc[ni][r] = 0.f;

            #pragma unroll
            for (int kk = 0; kk < 4; kk++) {
                const int c = kk * 16;
                #pragma unroll
                for (int ni = 0; ni < 8; ni++) {
                    uint32_t b0 = ldh2(ks + (ni * 8 + g) * 72 + c + 2 * tg);
                    uint32_t b1 = ldh2(ks + (ni * 8 + g) * 72 + c + 8 + 2 * tg);
                    mma_f16(sacc[ni], qf[kk][0], qf[kk][1], qf[kk][2], qf[kk][3], b0, b1);
                }
            }

            const bool need_mask = (kt * 64 + 63) > row_min;
            const int rloc[2] = {row_min + g, row_min + g + 8};

            #pragma unroll
            for (int rr = 0; rr < 2; rr++) {
                float mx = -1e30f;
                #pragma unroll
                for (int ni = 0; ni < 8; ni++) {
                    float v0 = sacc[ni][rr * 2 + 0];
                    float v1 = sacc[ni][rr * 2 + 1];
                    if (need_mask) {
                        int c0 = kt * 64 + ni * 8 + tg * 2;
                        if (c0     > rloc[rr]) v0 = -1e30f;
                        if (c0 + 1 > rloc[rr]) v1 = -1e30f;
                    }
                    sacc[ni][rr * 2 + 0] = v0;
                    sacc[ni][rr * 2 + 1] = v1;
                    mx = fmaxf(mx, fmaxf(v0, v1));
                }
                mx = fmaxf(mx, __shfl_xor_sync(0xffffffffu, mx, 1));
                mx = fmaxf(mx, __shfl_xor_sync(0xffffffffu, mx, 2));
                float mnew = fmaxf(mrow[rr], mx);
                float corr = __expf(mrow[rr] - mnew);
                float sum = 0.f;
                #pragma unroll
                for (int ni = 0; ni < 8; ni++) {
                    float e0 = __expf(sacc[ni][rr * 2 + 0] - mnew);
                    float e1 = __expf(sacc[ni][rr * 2 + 1] - mnew);
                    sacc[ni][rr * 2 + 0] = e0;
                    sacc[ni][rr * 2 + 1] = e1;
                    sum += e0 + e1;
                }
                sum += __shfl_xor_sync(0xffffffffu, sum, 1);
                sum += __shfl_xor_sync(0xffffffffu, sum, 2);
                lrow[rr] = lrow[rr] * corr + sum;
                mrow[rr] = mnew;
                #pragma unroll
                for (int di = 0; di < 8; di++) {
                    oacc[di][rr * 2 + 0] *= corr;
                    oacc[di][rr * 2 + 1] *= corr;
                }
            }

            // O += P @ V. P's A-fragment == S C-fragment layout (fp16 trick).
            #pragma unroll
            for (int kk = 0; kk < 4; kk++) {
                uint32_t a0 = pack_h2(sacc[2 * kk    ][0], sacc[2 * kk    ][1]);
                uint32_t a1 = pack_h2(sacc[2 * kk    ][2], sacc[2 * kk    ][3]);
                uint32_t a2 = pack_h2(sacc[2 * kk + 1][0], sacc[2 * kk + 1][1]);
                uint32_t a3 = pack_h2(sacc[2 * kk + 1][2], sacc[2 * kk + 1][3]);
                const int c = kk * 16;
                #pragma unroll
                for (int di = 0; di < 8; di++) {
                    uint32_t b0 = ldh2(vs + (di * 8 + g) * 72 + c + 2 * tg);
                    uint32_t b1 = ldh2(vs + (di * 8 + g) * 72 + c + 8 + 2 * tg);
                    mma_f16(oacc[di], a0, a1, a2, a3, b0, b1);
                }
            }
        }

        __syncthreads();   // all reads of stage s done before refill
        if (kt + 2 < nkt) prefetch_kv(s, kt + 2);
    }

    // write O (fp16: it is the A operand of the dense GEMM)
    float inv0 = 1.f / lrow[0], inv1 = 1.f / lrow[1];
    size_t row0 = (size_t)(b * SEQ + qt * 128 + warp * 16 + g);
    size_t row1 = row0 + 8;
    #pragma unroll
    for (int di = 0; di < 8; di++) {
        int c = h * 64 + di * 8 + tg * 2;
        *(uint32_t*)(O + row0 * HID + c) = pack_h2(oacc[di][0] * inv0, oacc[di][1] * inv0);
        *(uint32_t*)(O + row1 * HID + c) = pack_h2(oacc[di][2] * inv1, oacc[di][3] * inv1);
    }
}

// ---------------------------------------------------------------------------
extern "C" void kernel_launch(void* const* d_in, const int* in_sizes, int n_in,
                              void* d_out, int out_size)
{
    const float* hs     = (const float*)d_in[0];
    const float* cosb   = (const float*)d_in[1];
    const float* sinb   = (const float*)d_in[2];
    const float* wqkv   = (const float*)d_in[3];
    const float* wdense = (const float*)d_in[4];
    float* out = (float*)d_out;

    float* p_qkv;
    __half *p_hs, *p_wqkv, *p_wd, *p_q, *p_k, *p_vt, *p_attn;
    cudaGetSymbolAddress((void**)&p_qkv,  g_qkv);
    cudaGetSymbolAddress((void**)&p_hs,   g_hs_h);
    cudaGetSymbolAddress((void**)&p_wqkv, g_wqkv_h);
    cudaGetSymbolAddress((void**)&p_wd,   g_wd_h);
    cudaGetSymbolAddress((void**)&p_q,    g_q_h);
    cudaGetSymbolAddress((void**)&p_k,    g_k_h);
    cudaGetSymbolAddress((void**)&p_vt,   g_vt_h);
    cudaGetSymbolAddress((void**)&p_attn, g_attn_h);

    cudaFuncSetAttribute(gemm_f16_nt,
                         cudaFuncAttributeMaxDynamicSharedMemorySize, GEMM_SMEM);
    cudaFuncSetAttribute(flash_f16,
                         cudaFuncAttributeMaxDynamicSharedMemorySize, FA_SMEM);

    // 0) convert inputs to fp16
    f32_to_f16_kernel<<<(T_TOK * HID / 4 + 255) / 256, 256>>>(hs, p_hs, T_TOK * HID / 4);
    f32_to_f16_kernel<<<(QKV_N * HID / 4 + 255) / 256, 256>>>(wqkv, p_wqkv, QKV_N * HID / 4);
    f32_to_f16_kernel<<<(HID * HID / 4 + 255) / 256, 256>>>(wdense, p_wd, HID * HID / 4);

    // 1) QKV projection (fp16 in, fp32 out)
    {
        dim3 grid(QKV_N / 128, T_TOK / 128);
        gemm_f16_nt<<<grid, 256, GEMM_SMEM>>>(p_hs, p_wqkv, p_qkv, T_TOK, QKV_N, HID);
    }
    // 2) RoPE + split (emits fp16 q*0.125, k, V^T)
    rope_split_kernel<<<T_TOK, 256>>>(p_qkv, cosb, sinb, p_q, p_k, p_vt);

    // 3) causal flash attention (fp16 mma, P in registers)
    {
        dim3 grid(SEQ / 128, NHEAD, BATCH);
        flash_f16<<<grid, 256, FA_SMEM>>>(p_q, p_k, p_vt, p_attn);
    }
    // 4) dense projection (fp16 in, fp32 out)
    {
        dim3 grid(HID / 128, T_TOK / 128);
        gemm_f16_nt<<<grid, 256, GEMM_SMEM>>>(p_attn, p_wd, out, T_TOK, HID, HID);
    }
}

// round 8
// speedup vs baseline: 2.1773x; 1.0364x over previous
#include <cuda_runtime.h>
#include <cuda_fp16.h>
#include <cstdint>
#include <math.h>

#define T_TOK 4096
#define BATCH 2
#define SEQ   2048
#define NHEAD 32
#define HDIM  64
#define HID   2048
#define QKV_N 2176
#define ROPE_HALF 32

// ---------------- scratch (device globals; no allocation allowed) ----------
__device__ float  g_qkv   [T_TOK * QKV_N];          // qkv projection output (fp32)
__device__ __half g_hs_h  [T_TOK * HID];            // fp16 inputs
__device__ __half g_wqkv_h[QKV_N * HID];
__device__ __half g_wd_h  [HID * HID];
__device__ __half g_q_h   [T_TOK * HID];            // roped q * 0.125, fp16
__device__ __half g_k_h   [T_TOK * HDIM];           // roped k, fp16
__device__ __half g_vt_h  [BATCH * HDIM * SEQ];     // V transposed: [b][d][s], fp16
__device__ __half g_attn_h[T_TOK * HID];            // attention out, fp16

// ---------------- helpers ---------------------------------------------------
__device__ __forceinline__ void mma_f16(float* c,
    uint32_t a0, uint32_t a1, uint32_t a2, uint32_t a3,
    uint32_t b0, uint32_t b1)
{
    asm volatile(
        "mma.sync.aligned.m16n8k16.row.col.f32.f16.f16.f32 "
        "{%0,%1,%2,%3}, {%4,%5,%6,%7}, {%8,%9}, {%0,%1,%2,%3};"
        : "+f"(c[0]), "+f"(c[1]), "+f"(c[2]), "+f"(c[3])
        : "r"(a0), "r"(a1), "r"(a2), "r"(a3), "r"(b0), "r"(b1));
}

__device__ __forceinline__ void ldsm_x4(uint32_t& r0, uint32_t& r1,
                                        uint32_t& r2, uint32_t& r3, uint32_t addr)
{
    asm volatile("ldmatrix.sync.aligned.m8n8.x4.shared.b16 {%0,%1,%2,%3}, [%4];"
        : "=r"(r0), "=r"(r1), "=r"(r2), "=r"(r3) : "r"(addr));
}

__device__ __forceinline__ void cp_async16(uint32_t dst, const void* src) {
    asm volatile("cp.async.cg.shared.global [%0], [%1], 16;" :: "r"(dst), "l"(src));
}

__device__ __forceinline__ uint32_t pack_h2(float lo, float hi) {
    __half2 h = __floats2half2_rn(lo, hi);
    return *(uint32_t*)&h;
}

// ---------------------------------------------------------------------------
// fp32 -> fp16 conversion pass (bandwidth bound)
// ---------------------------------------------------------------------------
__global__ __launch_bounds__(256) void f32_to_f16_kernel(
    const float* __restrict__ src, __half* __restrict__ dst, int n4)
{
    int i = blockIdx.x * blockDim.x + threadIdx.x;
    if (i < n4) {
        float4 v = ((const float4*)src)[i];
        uint2 u;
        u.x = pack_h2(v.x, v.y);
        u.y = pack_h2(v.z, v.w);
        ((uint2*)dst)[i] = u;
    }
}

// ---------------------------------------------------------------------------
// FP16 GEMM (NT), ldmatrix fragment loads.
// BM=BN=128, BK=64, 256 threads (2x4 warps), 2-stage cp.async, 2 CTAs/SM.
// ---------------------------------------------------------------------------
#define GSTH (128 * 72)                 // halves per matrix stage
#define GEMM_SMEM (2 * 2 * GSTH * 2)    // 73728 B

__global__ __launch_bounds__(256, 2) void gemm_f16_nt(
    const __half* __restrict__ A, const __half* __restrict__ B,
    float* __restrict__ C, int M, int N, int K)
{
    extern __shared__ __half smh[];
    const int tid  = threadIdx.x;
    const int lane = tid & 31, warp = tid >> 5;
    const int g  = lane >> 2, tg = lane & 3;
    const int wm = warp >> 2, wn = warp & 3;
    const int bm = blockIdx.y * 128, bn = blockIdx.x * 128;

    const uint32_t as_base = (uint32_t)__cvta_generic_to_shared(smh);
    const uint32_t bs_base = as_base + 2 * GSTH * 2;

    // ldmatrix per-lane source rows/cols
    const int laneA_row = lane & 15;              // m row within 16
    const int laneA_col = (lane >> 4) * 8;        // k col: 0 or 8
    const int laneB_row = (lane & 7) + ((lane >> 4) << 3);   // n row within 16
    const int laneB_col = ((lane >> 3) & 1) * 8;  // k col: 0 or 8

    auto prefetch = [&](int stage, int k0) {
        #pragma unroll
        for (int l = 0; l < 4; l++) {
            int idx = l * 256 + tid;
            int row = idx >> 3, ch = (idx & 7) * 8;
            cp_async16(as_base + (uint32_t)(stage * GSTH + row * 72 + ch) * 2,
                       A + (size_t)(bm + row) * K + k0 + ch);
            cp_async16(bs_base + (uint32_t)(stage * GSTH + row * 72 + ch) * 2,
                       B + (size_t)(bn + row) * K + k0 + ch);
        }
        asm volatile("cp.async.commit_group;");
    };

    float acc[4][4][4];
    #pragma unroll
    for (int i = 0; i < 4; i++)
        #pragma unroll
        for (int j = 0; j < 4; j++)
            #pragma unroll
            for (int r = 0; r < 4; r++) acc[i][j][r] = 0.f;

    const int nK = K / 64;
    prefetch(0, 0);

    for (int kt = 0; kt < nK; kt++) {
        int s = kt & 1;
        if (kt + 1 < nK) {
            prefetch(s ^ 1, (kt + 1) * 64);
            asm volatile("cp.async.wait_group 1;");
        } else {
            asm volatile("cp.async.wait_group 0;");
        }
        __syncthreads();

        const uint32_t a_st = as_base + (uint32_t)(s * GSTH) * 2;
        const uint32_t b_st = bs_base + (uint32_t)(s * GSTH) * 2;

        #pragma unroll
        for (int kk = 0; kk < 4; kk++) {
            const int c = kk * 16;
            uint32_t af[4][4], bf[4][2];
            #pragma unroll
            for (int mi = 0; mi < 4; mi++) {
                uint32_t addr = a_st +
                    (uint32_t)((wm * 64 + mi * 16 + laneA_row) * 72 + c + laneA_col) * 2;
                ldsm_x4(af[mi][0], af[mi][1], af[mi][2], af[mi][3], addr);
            }
            #pragma unroll
            for (int p = 0; p < 2; p++) {
                uint32_t addr = b_st +
                    (uint32_t)((wn * 32 + p * 16 + laneB_row) * 72 + c + laneB_col) * 2;
                ldsm_x4(bf[2 * p][0], bf[2 * p][1], bf[2 * p + 1][0], bf[2 * p + 1][1], addr);
            }
            #pragma unroll
            for (int mi = 0; mi < 4; mi++)
                #pragma unroll
                for (int ni = 0; ni < 4; ni++)
                    mma_f16(acc[mi][ni], af[mi][0], af[mi][1], af[mi][2], af[mi][3],
                            bf[ni][0], bf[ni][1]);
        }
        __syncthreads();
    }

    #pragma unroll
    for (int mi = 0; mi < 4; mi++) {
        size_t r0 = (size_t)(bm + wm * 64 + mi * 16 + g);
        #pragma unroll
        for (int ni = 0; ni < 4; ni++) {
            int c = bn + wn * 32 + ni * 8 + tg * 2;
            *(float2*)(C + r0 * N + c)       = make_float2(acc[mi][ni][0], acc[mi][ni][1]);
            *(float2*)(C + (r0 + 8) * N + c) = make_float2(acc[mi][ni][2], acc[mi][ni][3]);
        }
    }
}

// ---------------------------------------------------------------------------
// RoPE + split. Emits fp16: q (pre-scaled by 0.125), k, and V transposed.
// ---------------------------------------------------------------------------
__global__ __launch_bounds__(256) void rope_split_kernel(
    const float* __restrict__ qkv,
    const float* __restrict__ cosb, const float* __restrict__ sinb,
    __half* __restrict__ q, __half* __restrict__ k, __half* __restrict__ vt)
{
    const int t = blockIdx.x;
    const int bb = t >> 11;
    const int ss = t & (SEQ - 1);
    const float* row = qkv + (size_t)t * QKV_N;
    const float* cs  = cosb + t * ROPE_HALF;
    const float* sn  = sinb + t * ROPE_HALF;

    for (int i = threadIdx.x; i < NHEAD * ROPE_HALF; i += blockDim.x) {
        int hh = i >> 5, d = i & 31;
        float c = cs[d], s = sn[d];
        float x1 = row[hh * HDIM + d];
        float x2 = row[hh * HDIM + d + ROPE_HALF];
        q[(size_t)t * HID + hh * HDIM + d]             = __float2half_rn((x1 * c - x2 * s) * 0.125f);
        q[(size_t)t * HID + hh * HDIM + d + ROPE_HALF] = __float2half_rn((x2 * c + x1 * s) * 0.125f);
    }
    for (int i = threadIdx.x; i < ROPE_HALF; i += blockDim.x) {
        float c = cs[i], s = sn[i];
        float x1 = row[HID + i];
        float x2 = row[HID + i + ROPE_HALF];
        k[(size_t)t * HDIM + i]             = __float2half_rn(x1 * c - x2 * s);
        k[(size_t)t * HDIM + i + ROPE_HALF] = __float2half_rn(x2 * c + x1 * s);
    }
    for (int i = threadIdx.x; i < HDIM; i += blockDim.x) {
        vt[((size_t)(bb * HDIM + i)) * SEQ + ss] = __float2half_rn(row[HID + HDIM + i]);
    }
}

// ---------------------------------------------------------------------------
// Causal flash attention, fp16 mma + ldmatrix. BM=128 (8 warps), BN=64,
// double-buffered K/Vt, P stays in registers.
// smem (halves): Ks[2][64][72], Vs[2][64][72], Qs[128][72].
// ---------------------------------------------------------------------------
#define KST (64 * 72)
#define FA_SMEM ((4 * KST + 128 * 72) * 2)   // 55296 B

__global__ __launch_bounds__(256, 2) void flash_f16(
    const __half* __restrict__ Q, const __half* __restrict__ Kg,
    const __half* __restrict__ Vt, __half* __restrict__ O)
{
    extern __shared__ __half smh[];
    const int tid  = threadIdx.x;
    const int lane = tid & 31, warp = tid >> 5;
    const int g = lane >> 2, tg = lane & 3;
    const int qt = blockIdx.x, h = blockIdx.y, b = blockIdx.z;
    const int nkt = 2 * qt + 2;
    const int row_min = qt * 128 + warp * 16;

    const int laneA_row = lane & 15;
    const int laneA_col = (lane >> 4) * 8;
    const int laneB_row = (lane & 7) + ((lane >> 4) << 3);
    const int laneB_col = ((lane >> 3) & 1) * 8;

    const uint32_t sm_base = (uint32_t)__cvta_generic_to_shared(smh);
    const uint32_t qp_base = sm_base + 4 * KST * 2;

    // Q tile -> smem (group 0)
    for (int i = tid; i < 1024; i += 256) {
        int r = i >> 3, ch = (i & 7) * 8;
        cp_async16(qp_base + (uint32_t)(r * 72 + ch) * 2,
                   Q + ((size_t)(b * SEQ + qt * 128 + r) * NHEAD + h) * HDIM + ch);
    }
    asm volatile("cp.async.commit_group;");

    auto prefetch_kv = [&](int s, int kt) {
        #pragma unroll
        for (int i = tid; i < 512; i += 256) {
            int r = i >> 3, ch = (i & 7) * 8;
            cp_async16(sm_base + (uint32_t)(s * KST + r * 72 + ch) * 2,
                       Kg + (size_t)(b * SEQ + kt * 64 + r) * HDIM + ch);
            cp_async16(sm_base + (uint32_t)((2 + s) * KST + r * 72 + ch) * 2,
                       Vt + ((size_t)(b * HDIM + r)) * SEQ + kt * 64 + ch);
        }
        asm volatile("cp.async.commit_group;");
    };

    prefetch_kv(0, 0);
    prefetch_kv(1, 1);

    asm volatile("cp.async.wait_group 2;");   // Q arrived
    __syncthreads();

    // Q fragments via ldmatrix (invariant across KV tiles)
    uint32_t qf[4][4];
    {
        #pragma unroll
        for (int kk = 0; kk < 4; kk++) {
            uint32_t addr = qp_base +
                (uint32_t)((warp * 16 + laneA_row) * 72 + kk * 16 + laneA_col) * 2;
            ldsm_x4(qf[kk][0], qf[kk][1], qf[kk][2], qf[kk][3], addr);
        }
    }

    float oacc[8][4];
    #pragma unroll
    for (int d = 0; d < 8; d++)
        #pragma unroll
        for (int r = 0; r < 4; r++) oacc[d][r] = 0.f;
    float mrow[2] = {-1e30f, -1e30f};
    float lrow[2] = {0.f, 0.f};

    for (int kt = 0; kt < nkt; kt++) {
        const int s = kt & 1;
        if (kt + 1 < nkt) asm volatile("cp.async.wait_group 1;");
        else              asm volatile("cp.async.wait_group 0;");
        __syncthreads();

        const bool skip = (kt * 64) > (row_min + 15);
        if (!skip) {
            const uint32_t k_st = sm_base + (uint32_t)(s * KST) * 2;
            const uint32_t v_st = sm_base + (uint32_t)((2 + s) * KST) * 2;

            // S = (Q*0.125) K^T
            float sacc[8][4];
            #pragma unroll
            for (int ni = 0; ni < 8; ni++)
                #pragma unroll
                for (int r = 0; r < 4; r++) sacc[ni][r] = 0.f;

            #pragma unroll
            for (int kk = 0; kk < 4; kk++) {
                const int c = kk * 16;
                uint32_t bf[8][2];
                #pragma unroll
                for (int p = 0; p < 4; p++) {
                    uint32_t addr = k_st +
                        (uint32_t)((p * 16 + laneB_row) * 72 + c + laneB_col) * 2;
                    ldsm_x4(bf[2 * p][0], bf[2 * p][1], bf[2 * p + 1][0], bf[2 * p + 1][1], addr);
                }
                #pragma unroll
                for (int ni = 0; ni < 8; ni++)
                    mma_f16(sacc[ni], qf[kk][0], qf[kk][1], qf[kk][2], qf[kk][3],
                            bf[ni][0], bf[ni][1]);
            }

            const bool need_mask = (kt * 64 + 63) > row_min;
            const int rloc[2] = {row_min + g, row_min + g + 8};

            #pragma unroll
            for (int rr = 0; rr < 2; rr++) {
                float mx = -1e30f;
                #pragma unroll
                for (int ni = 0; ni < 8; ni++) {
                    float v0 = sacc[ni][rr * 2 + 0];
                    float v1 = sacc[ni][rr * 2 + 1];
                    if (need_mask) {
                        int c0 = kt * 64 + ni * 8 + tg * 2;
                        if (c0     > rloc[rr]) v0 = -1e30f;
                        if (c0 + 1 > rloc[rr]) v1 = -1e30f;
                    }
                    sacc[ni][rr * 2 + 0] = v0;
                    sacc[ni][rr * 2 + 1] = v1;
                    mx = fmaxf(mx, fmaxf(v0, v1));
                }
                mx = fmaxf(mx, __shfl_xor_sync(0xffffffffu, mx, 1));
                mx = fmaxf(mx, __shfl_xor_sync(0xffffffffu, mx, 2));
                float mnew = fmaxf(mrow[rr], mx);
                float corr = __expf(mrow[rr] - mnew);
                float sum = 0.f;
                #pragma unroll
                for (int ni = 0; ni < 8; ni++) {
                    float e0 = __expf(sacc[ni][rr * 2 + 0] - mnew);
                    float e1 = __expf(sacc[ni][rr * 2 + 1] - mnew);
                    sacc[ni][rr * 2 + 0] = e0;
                    sacc[ni][rr * 2 + 1] = e1;
                    sum += e0 + e1;
                }
                sum += __shfl_xor_sync(0xffffffffu, sum, 1);
                sum += __shfl_xor_sync(0xffffffffu, sum, 2);
                lrow[rr] = lrow[rr] * corr + sum;
                mrow[rr] = mnew;
                #pragma unroll
                for (int di = 0; di < 8; di++) {
                    oacc[di][rr * 2 + 0] *= corr;
                    oacc[di][rr * 2 + 1] *= corr;
                }
            }

            // O += P @ V. P's A-fragment == S C-fragment layout (fp16 trick).
            #pragma unroll
            for (int kk = 0; kk < 4; kk++) {
                uint32_t a0 = pack_h2(sacc[2 * kk    ][0], sacc[2 * kk    ][1]);
                uint32_t a1 = pack_h2(sacc[2 * kk    ][2], sacc[2 * kk    ][3]);
                uint32_t a2 = pack_h2(sacc[2 * kk + 1][0], sacc[2 * kk + 1][1]);
                uint32_t a3 = pack_h2(sacc[2 * kk + 1][2], sacc[2 * kk + 1][3]);
                const int c = kk * 16;
                uint32_t vf[8][2];
                #pragma unroll
                for (int p = 0; p < 4; p++) {
                    uint32_t addr = v_st +
                        (uint32_t)((p * 16 + laneB_row) * 72 + c + laneB_col) * 2;
                    ldsm_x4(vf[2 * p][0], vf[2 * p][1], vf[2 * p + 1][0], vf[2 * p + 1][1], addr);
                }
                #pragma unroll
                for (int di = 0; di < 8; di++)
                    mma_f16(oacc[di], a0, a1, a2, a3, vf[di][0], vf[di][1]);
            }
        }

        __syncthreads();   // all reads of stage s done before refill
        if (kt + 2 < nkt) prefetch_kv(s, kt + 2);
    }

    // write O (fp16: A operand of the dense GEMM)
    float inv0 = 1.f / lrow[0], inv1 = 1.f / lrow[1];
    size_t row0 = (size_t)(b * SEQ + qt * 128 + warp * 16 + g);
    size_t row1 = row0 + 8;
    #pragma unroll
    for (int di = 0; di < 8; di++) {
        int c = h * 64 + di * 8 + tg * 2;
        *(uint32_t*)(O + row0 * HID + c) = pack_h2(oacc[di][0] * inv0, oacc[di][1] * inv0);
        *(uint32_t*)(O + row1 * HID + c) = pack_h2(oacc[di][2] * inv1, oacc[di][3] * inv1);
    }
}

// ---------------------------------------------------------------------------
extern "C" void kernel_launch(void* const* d_in, const int* in_sizes, int n_in,
                              void* d_out, int out_size)
{
    const float* hs     = (const float*)d_in[0];
    const float* cosb   = (const float*)d_in[1];
    const float* sinb   = (const float*)d_in[2];
    const float* wqkv   = (const float*)d_in[3];
    const float* wdense = (const float*)d_in[4];
    float* out = (float*)d_out;

    float* p_qkv;
    __half *p_hs, *p_wqkv, *p_wd, *p_q, *p_k, *p_vt, *p_attn;
    cudaGetSymbolAddress((void**)&p_qkv,  g_qkv);
    cudaGetSymbolAddress((void**)&p_hs,   g_hs_h);
    cudaGetSymbolAddress((void**)&p_wqkv, g_wqkv_h);
    cudaGetSymbolAddress((void**)&p_wd,   g_wd_h);
    cudaGetSymbolAddress((void**)&p_q,    g_q_h);
    cudaGetSymbolAddress((void**)&p_k,    g_k_h);
    cudaGetSymbolAddress((void**)&p_vt,   g_vt_h);
    cudaGetSymbolAddress((void**)&p_attn, g_attn_h);

    cudaFuncSetAttribute(gemm_f16_nt,
                         cudaFuncAttributeMaxDynamicSharedMemorySize, GEMM_SMEM);
    cudaFuncSetAttribute(flash_f16,
                         cudaFuncAttributeMaxDynamicSharedMemorySize, FA_SMEM);

    // 0) convert inputs to fp16
    f32_to_f16_kernel<<<(T_TOK * HID / 4 + 255) / 256, 256>>>(hs, p_hs, T_TOK * HID / 4);
    f32_to_f16_kernel<<<(QKV_N * HID / 4 + 255) / 256, 256>>>(wqkv, p_wqkv, QKV_N * HID / 4);
    f32_to_f16_kernel<<<(HID * HID / 4 + 255) / 256, 256>>>(wdense, p_wd, HID * HID / 4);

    // 1) QKV projection (fp16 in, fp32 out)
    {
        dim3 grid(QKV_N / 128, T_TOK / 128);
        gemm_f16_nt<<<grid, 256, GEMM_SMEM>>>(p_hs, p_wqkv, p_qkv, T_TOK, QKV_N, HID);
    }
    // 2) RoPE + split (emits fp16 q*0.125, k, V^T)
    rope_split_kernel<<<T_TOK, 256>>>(p_qkv, cosb, sinb, p_q, p_k, p_vt);

    // 3) causal flash attention (fp16 mma + ldmatrix, P in registers)
    {
        dim3 grid(SEQ / 128, NHEAD, BATCH);
        flash_f16<<<grid, 256, FA_SMEM>>>(p_q, p_k, p_vt, p_attn);
    }
    // 4) dense projection (fp16 in, fp32 out)
    {
        dim3 grid(HID / 128, T_TOK / 128);
        gemm_f16_nt<<<grid, 256, GEMM_SMEM>>>(p_attn, p_wd, out, T_TOK, HID, HID);
    }
}

// round 10
// speedup vs baseline: 2.3032x; 1.0578x over previous
#include <cuda_runtime.h>
#include <cuda_fp16.h>
#include <cstdint>
#include <math.h>

#define T_TOK 4096
#define BATCH 2
#define SEQ   2048
#define NHEAD 32
#define HDIM  64
#define HID   2048
#define QKV_N 2176
#define ROPE_HALF 32

// ---------------- scratch (device globals; no allocation allowed) ----------
__device__ float  g_qkv   [T_TOK * QKV_N];          // qkv projection output (fp32)
__device__ __half g_hs_h  [T_TOK * HID];            // fp16 inputs
__device__ __half g_wqkv_h[QKV_N * HID];
__device__ __half g_wd_h  [HID * HID];
__device__ __half g_q_h   [T_TOK * HID];            // roped q * 0.125*log2e, fp16
__device__ __half g_k_h   [T_TOK * HDIM];           // roped k, fp16
__device__ __half g_vt_h  [BATCH * HDIM * SEQ];     // V transposed: [b][d][s], fp16
__device__ __half g_attn_h[T_TOK * HID];            // attention out, fp16

// ---------------- helpers ---------------------------------------------------
__device__ __forceinline__ void mma_f16(float* c,
    uint32_t a0, uint32_t a1, uint32_t a2, uint32_t a3,
    uint32_t b0, uint32_t b1)
{
    asm volatile(
        "mma.sync.aligned.m16n8k16.row.col.f32.f16.f16.f32 "
        "{%0,%1,%2,%3}, {%4,%5,%6,%7}, {%8,%9}, {%0,%1,%2,%3};"
        : "+f"(c[0]), "+f"(c[1]), "+f"(c[2]), "+f"(c[3])
        : "r"(a0), "r"(a1), "r"(a2), "r"(a3), "r"(b0), "r"(b1));
}

__device__ __forceinline__ void ldsm_x4(uint32_t& r0, uint32_t& r1,
                                        uint32_t& r2, uint32_t& r3, uint32_t addr)
{
    asm volatile("ldmatrix.sync.aligned.m8n8.x4.shared.b16 {%0,%1,%2,%3}, [%4];"
        : "=r"(r0), "=r"(r1), "=r"(r2), "=r"(r3) : "r"(addr));
}

__device__ __forceinline__ void cp_async16(uint32_t dst, const void* src) {
    asm volatile("cp.async.cg.shared.global [%0], [%1], 16;" :: "r"(dst), "l"(src));
}

__device__ __forceinline__ uint32_t pack_h2(float lo, float hi) {
    __half2 h = __floats2half2_rn(lo, hi);
    return *(uint32_t*)&h;
}

__device__ __forceinline__ float fast_exp2(float x) {
    float y;
    asm("ex2.approx.ftz.f32 %0, %1;" : "=f"(y) : "f"(x));
    return y;
}

// ---------------------------------------------------------------------------
// fp32 -> fp16 conversion pass (bandwidth bound)
// ---------------------------------------------------------------------------
__global__ __launch_bounds__(256) void f32_to_f16_kernel(
    const float* __restrict__ src, __half* __restrict__ dst, int n4)
{
    int i = blockIdx.x * blockDim.x + threadIdx.x;
    if (i < n4) {
        float4 v = ((const float4*)src)[i];
        uint2 u;
        u.x = pack_h2(v.x, v.y);
        u.y = pack_h2(v.z, v.w);
        ((uint2*)dst)[i] = u;
    }
}

// ---------------------------------------------------------------------------
// FP16 GEMM (NT), ldmatrix fragment loads, 3-stage cp.async pipeline with a
// SINGLE __syncthreads per K-iteration (CUTLASS multistage schedule).
// BM=BN=128, BK=64, 256 threads (2x4 warps), 2 CTAs/SM.
// ---------------------------------------------------------------------------
#define GSTH (128 * 72)                 // halves per matrix stage
#define GEMM_SMEM (3 * 2 * GSTH * 2)    // 110592 B

__global__ __launch_bounds__(256, 2) void gemm_f16_nt(
    const __half* __restrict__ A, const __half* __restrict__ B,
    float* __restrict__ C, int M, int N, int K)
{
    extern __shared__ __half smh[];
    const int tid  = threadIdx.x;
    const int lane = tid & 31, warp = tid >> 5;
    const int g  = lane >> 2, tg = lane & 3;
    const int wm = warp >> 2, wn = warp & 3;
    const int bm = blockIdx.y * 128, bn = blockIdx.x * 128;

    const uint32_t as_base = (uint32_t)__cvta_generic_to_shared(smh);
    const uint32_t bs_base = as_base + 3 * GSTH * 2;

    const int laneA_row = lane & 15;
    const int laneA_col = (lane >> 4) * 8;
    const int laneB_row = (lane & 7) + ((lane >> 4) << 3);
    const int laneB_col = ((lane >> 3) & 1) * 8;

    auto prefetch = [&](int stage, int k0) {
        #pragma unroll
        for (int l = 0; l < 4; l++) {
            int idx = l * 256 + tid;
            int row = idx >> 3, ch = (idx & 7) * 8;
            cp_async16(as_base + (uint32_t)(stage * GSTH + row * 72 + ch) * 2,
                       A + (size_t)(bm + row) * K + k0 + ch);
            cp_async16(bs_base + (uint32_t)(stage * GSTH + row * 72 + ch) * 2,
                       B + (size_t)(bn + row) * K + k0 + ch);
        }
        asm volatile("cp.async.commit_group;");
    };

    float acc[4][4][4];
    #pragma unroll
    for (int i = 0; i < 4; i++)
        #pragma unroll
        for (int j = 0; j < 4; j++)
            #pragma unroll
            for (int r = 0; r < 4; r++) acc[i][j][r] = 0.f;

    const int nK = K / 64;
    prefetch(0, 0);
    prefetch(1, 64);

    for (int kt = 0; kt < nK; kt++) {
        const int s = kt % 3;
        if (kt + 1 < nK) asm volatile("cp.async.wait_group 1;");
        else             asm volatile("cp.async.wait_group 0;");
        __syncthreads();
        // Refill target stage was last read just before this barrier -> safe.
        if (kt + 2 < nK) prefetch((kt + 2) % 3, (kt + 2) * 64);

        const uint32_t a_st = as_base + (uint32_t)(s * GSTH) * 2;
        const uint32_t b_st = bs_base + (uint32_t)(s * GSTH) * 2;

        #pragma unroll
        for (int kk = 0; kk < 4; kk++) {
            const int c = kk * 16;
            uint32_t af[4][4], bf[4][2];
            #pragma unroll
            for (int mi = 0; mi < 4; mi++) {
                uint32_t addr = a_st +
                    (uint32_t)((wm * 64 + mi * 16 + laneA_row) * 72 + c + laneA_col) * 2;
                ldsm_x4(af[mi][0], af[mi][1], af[mi][2], af[mi][3], addr);
            }
            #pragma unroll
            for (int p = 0; p < 2; p++) {
                uint32_t addr = b_st +
                    (uint32_t)((wn * 32 + p * 16 + laneB_row) * 72 + c + laneB_col) * 2;
                ldsm_x4(bf[2 * p][0], bf[2 * p][1], bf[2 * p + 1][0], bf[2 * p + 1][1], addr);
            }
            #pragma unroll
            for (int mi = 0; mi < 4; mi++)
                #pragma unroll
                for (int ni = 0; ni < 4; ni++)
                    mma_f16(acc[mi][ni], af[mi][0], af[mi][1], af[mi][2], af[mi][3],
                            bf[ni][0], bf[ni][1]);
        }
    }

    #pragma unroll
    for (int mi = 0; mi < 4; mi++) {
        size_t r0 = (size_t)(bm + wm * 64 + mi * 16 + g);
        #pragma unroll
        for (int ni = 0; ni < 4; ni++) {
            int c = bn + wn * 32 + ni * 8 + tg * 2;
            *(float2*)(C + r0 * N + c)       = make_float2(acc[mi][ni][0], acc[mi][ni][1]);
            *(float2*)(C + (r0 + 8) * N + c) = make_float2(acc[mi][ni][2], acc[mi][ni][3]);
        }
    }
}

// ---------------------------------------------------------------------------
// RoPE + split. Emits fp16: q (pre-scaled by 0.125*log2e for ex2 softmax),
// k, and V transposed.
// ---------------------------------------------------------------------------
__global__ __launch_bounds__(256) void rope_split_kernel(
    const float* __restrict__ qkv,
    const float* __restrict__ cosb, const float* __restrict__ sinb,
    __half* __restrict__ q, __half* __restrict__ k, __half* __restrict__ vt)
{
    const int t = blockIdx.x;
    const int bb = t >> 11;
    const int ss = t & (SEQ - 1);
    const float* row = qkv + (size_t)t * QKV_N;
    const float* cs  = cosb + t * ROPE_HALF;
    const float* sn  = sinb + t * ROPE_HALF;
    const float QS = 0.125f * 1.4426950408889634f;   // scale * log2(e)

    for (int i = threadIdx.x; i < NHEAD * ROPE_HALF; i += blockDim.x) {
        int hh = i >> 5, d = i & 31;
        float c = cs[d], s = sn[d];
        float x1 = row[hh * HDIM + d];
        float x2 = row[hh * HDIM + d + ROPE_HALF];
        q[(size_t)t * HID + hh * HDIM + d]             = __float2half_rn((x1 * c - x2 * s) * QS);
        q[(size_t)t * HID + hh * HDIM + d + ROPE_HALF] = __float2half_rn((x2 * c + x1 * s) * QS);
    }
    for (int i = threadIdx.x; i < ROPE_HALF; i += blockDim.x) {
        float c = cs[i], s = sn[i];
        float x1 = row[HID + i];
        float x2 = row[HID + i + ROPE_HALF];
        k[(size_t)t * HDIM + i]             = __float2half_rn(x1 * c - x2 * s);
        k[(size_t)t * HDIM + i + ROPE_HALF] = __float2half_rn(x2 * c + x1 * s);
    }
    for (int i = threadIdx.x; i < HDIM; i += blockDim.x) {
        vt[((size_t)(bb * HDIM + i)) * SEQ + ss] = __float2half_rn(row[HID + HDIM + i]);
    }
}

// ---------------------------------------------------------------------------
// Causal flash attention, fp16 mma + ldmatrix. BM=128 (8 warps), BN=64.
// 3-stage KV ring with ONE __syncthreads per tile; heavy-first q-tile order;
// ex2-based softmax (log2e folded into Q).
// smem (halves): [K0 V0 K1 V1 K2 V2] each 64x72, then Q 128x72.
// ---------------------------------------------------------------------------
#define KST (64 * 72)
#define FA_SMEM ((6 * KST + 128 * 72) * 2)   // 73728 B

__global__ __launch_bounds__(256, 2) void flash_f16(
    const __half* __restrict__ Q, const __half* __restrict__ Kg,
    const __half* __restrict__ Vt, __half* __restrict__ O)
{
    extern __shared__ __half smh[];
    const int tid  = threadIdx.x;
    const int lane = tid & 31, warp = tid >> 5;
    const int g = lane >> 2, tg = lane & 3;
    const int qt = (int)gridDim.x - 1 - (int)blockIdx.x;   // heavy tiles first
    const int h = blockIdx.y, b = blockIdx.z;
    const int nkt = 2 * qt + 2;
    const int row_min = qt * 128 + warp * 16;

    const int laneA_row = lane & 15;
    const int laneA_col = (lane >> 4) * 8;
    const int laneB_row = (lane & 7) + ((lane >> 4) << 3);
    const int laneB_col = ((lane >> 3) & 1) * 8;

    const uint32_t sm_base = (uint32_t)__cvta_generic_to_shared(smh);
    const uint32_t qp_base = sm_base + 6 * KST * 2;

    // Q tile -> smem (group 0)
    for (int i = tid; i < 1024; i += 256) {
        int r = i >> 3, ch = (i & 7) * 8;
        cp_async16(qp_base + (uint32_t)(r * 72 + ch) * 2,
                   Q + ((size_t)(b * SEQ + qt * 128 + r) * NHEAD + h) * HDIM + ch);
    }
    asm volatile("cp.async.commit_group;");

    auto prefetch_kv = [&](int s, int kt) {
        #pragma unroll
        for (int i = tid; i < 512; i += 256) {
            int r = i >> 3, ch = (i & 7) * 8;
            cp_async16(sm_base + (uint32_t)(s * 2 * KST + r * 72 + ch) * 2,
                       Kg + (size_t)(b * SEQ + kt * 64 + r) * HDIM + ch);
            cp_async16(sm_base + (uint32_t)((s * 2 + 1) * KST + r * 72 + ch) * 2,
                       Vt + ((size_t)(b * HDIM + r)) * SEQ + kt * 64 + ch);
        }
        asm volatile("cp.async.commit_group;");
    };

    prefetch_kv(0, 0);
    prefetch_kv(1, 1);

    asm volatile("cp.async.wait_group 2;");   // Q arrived
    __syncthreads();

    uint32_t qf[4][4];
    {
        #pragma unroll
        for (int kk = 0; kk < 4; kk++) {
            uint32_t addr = qp_base +
                (uint32_t)((warp * 16 + laneA_row) * 72 + kk * 16 + laneA_col) * 2;
            ldsm_x4(qf[kk][0], qf[kk][1], qf[kk][2], qf[kk][3], addr);
        }
    }

    float oacc[8][4];
    #pragma unroll
    for (int d = 0; d < 8; d++)
        #pragma unroll
        for (int r = 0; r < 4; r++) oacc[d][r] = 0.f;
    float mrow[2] = {-1e30f, -1e30f};
    float lrow[2] = {0.f, 0.f};

    for (int kt = 0; kt < nkt; kt++) {
        const int s = kt % 3;
        if (kt + 1 < nkt) asm volatile("cp.async.wait_group 1;");
        else              asm volatile("cp.async.wait_group 0;");
        __syncthreads();
        if (kt + 2 < nkt) prefetch_kv((kt + 2) % 3, kt + 2);

        const bool skip = (kt * 64) > (row_min + 15);
        if (!skip) {
            const uint32_t k_st = sm_base + (uint32_t)(s * 2 * KST) * 2;
            const uint32_t v_st = sm_base + (uint32_t)((s * 2 + 1) * KST) * 2;

            // S (in log2 units: Q pre-scaled by 0.125*log2e)
            float sacc[8][4];
            #pragma unroll
            for (int ni = 0; ni < 8; ni++)
                #pragma unroll
                for (int r = 0; r < 4; r++) sacc[ni][r] = 0.f;

            #pragma unroll
            for (int kk = 0; kk < 4; kk++) {
                const int c = kk * 16;
                uint32_t bf[8][2];
                #pragma unroll
                for (int p = 0; p < 4; p++) {
                    uint32_t addr = k_st +
                        (uint32_t)((p * 16 + laneB_row) * 72 + c + laneB_col) * 2;
                    ldsm_x4(bf[2 * p][0], bf[2 * p][1], bf[2 * p + 1][0], bf[2 * p + 1][1], addr);
                }
                #pragma unroll
                for (int ni = 0; ni < 8; ni++)
                    mma_f16(sacc[ni], qf[kk][0], qf[kk][1], qf[kk][2], qf[kk][3],
                            bf[ni][0], bf[ni][1]);
            }

            const bool need_mask = (kt * 64 + 63) > row_min;
            const int rloc[2] = {row_min + g, row_min + g + 8};

            #pragma unroll
            for (int rr = 0; rr < 2; rr++) {
                float mx = -1e30f;
                #pragma unroll
                for (int ni = 0; ni < 8; ni++) {
                    float v0 = sacc[ni][rr * 2 + 0];
                    float v1 = sacc[ni][rr * 2 + 1];
                    if (need_mask) {
                        int c0 = kt * 64 + ni * 8 + tg * 2;
                        if (c0     > rloc[rr]) v0 = -1e30f;
                        if (c0 + 1 > rloc[rr]) v1 = -1e30f;
                    }
                    sacc[ni][rr * 2 + 0] = v0;
                    sacc[ni][rr * 2 + 1] = v1;
                    mx = fmaxf(mx, fmaxf(v0, v1));
                }
                mx = fmaxf(mx, __shfl_xor_sync(0xffffffffu, mx, 1));
                mx = fmaxf(mx, __shfl_xor_sync(0xffffffffu, mx, 2));
                float mnew = fmaxf(mrow[rr], mx);
                float corr = fast_exp2(mrow[rr] - mnew);
                float sum = 0.f;
                #pragma unroll
                for (int ni = 0; ni < 8; ni++) {
                    float e0 = fast_exp2(sacc[ni][rr * 2 + 0] - mnew);
                    float e1 = fast_exp2(sacc[ni][rr * 2 + 1] - mnew);
                    sacc[ni][rr * 2 + 0] = e0;
                    sacc[ni][rr * 2 + 1] = e1;
                    sum += e0 + e1;
                }
                sum += __shfl_xor_sync(0xffffffffu, sum, 1);
                sum += __shfl_xor_sync(0xffffffffu, sum, 2);
                lrow[rr] = lrow[rr] * corr + sum;
                mrow[rr] = mnew;
                #pragma unroll
                for (int di = 0; di < 8; di++) {
                    oacc[di][rr * 2 + 0] *= corr;
                    oacc[di][rr * 2 + 1] *= corr;
                }
            }

            // O += P @ V  (P's A-fragment == S C-fragment layout)
            #pragma unroll
            for (int kk = 0; kk < 4; kk++) {
                uint32_t a0 = pack_h2(sacc[2 * kk    ][0], sacc[2 * kk    ][1]);
                uint32_t a1 = pack_h2(sacc[2 * kk    ][2], sacc[2 * kk    ][3]);
                uint32_t a2 = pack_h2(sacc[2 * kk + 1][0], sacc[2 * kk + 1][1]);
                uint32_t a3 = pack_h2(sacc[2 * kk + 1][2], sacc[2 * kk + 1][3]);
                const int c = kk * 16;
                uint32_t vf[8][2];
                #pragma unroll
                for (int p = 0; p < 4; p++) {
                    uint32_t addr = v_st +
                        (uint32_t)((p * 16 + laneB_row) * 72 + c + laneB_col) * 2;
                    ldsm_x4(vf[2 * p][0], vf[2 * p][1], vf[2 * p + 1][0], vf[2 * p + 1][1], addr);
                }
                #pragma unroll
                for (int di = 0; di < 8; di++)
                    mma_f16(oacc[di], a0, a1, a2, a3, vf[di][0], vf[di][1]);
            }
        }
    }

    // write O (fp16: A operand of the dense GEMM)
    float inv0 = 1.f / lrow[0], inv1 = 1.f / lrow[1];
    size_t row0 = (size_t)(b * SEQ + qt * 128 + warp * 16 + g);
    size_t row1 = row0 + 8;
    #pragma unroll
    for (int di = 0; di < 8; di++) {
        int c = h * 64 + di * 8 + tg * 2;
        *(uint32_t*)(O + row0 * HID + c) = pack_h2(oacc[di][0] * inv0, oacc[di][1] * inv0);
        *(uint32_t*)(O + row1 * HID + c) = pack_h2(oacc[di][2] * inv1, oacc[di][3] * inv1);
    }
}

// ---------------------------------------------------------------------------
extern "C" void kernel_launch(void* const* d_in, const int* in_sizes, int n_in,
                              void* d_out, int out_size)
{
    const float* hs     = (const float*)d_in[0];
    const float* cosb   = (const float*)d_in[1];
    const float* sinb   = (const float*)d_in[2];
    const float* wqkv   = (const float*)d_in[3];
    const float* wdense = (const float*)d_in[4];
    float* out = (float*)d_out;

    float* p_qkv;
    __half *p_hs, *p_wqkv, *p_wd, *p_q, *p_k, *p_vt, *p_attn;
    cudaGetSymbolAddress((void**)&p_qkv,  g_qkv);
    cudaGetSymbolAddress((void**)&p_hs,   g_hs_h);
    cudaGetSymbolAddress((void**)&p_wqkv, g_wqkv_h);
    cudaGetSymbolAddress((void**)&p_wd,   g_wd_h);
    cudaGetSymbolAddress((void**)&p_q,    g_q_h);
    cudaGetSymbolAddress((void**)&p_k,    g_k_h);
    cudaGetSymbolAddress((void**)&p_vt,   g_vt_h);
    cudaGetSymbolAddress((void**)&p_attn, g_attn_h);

    cudaFuncSetAttribute(gemm_f16_nt,
                         cudaFuncAttributeMaxDynamicSharedMemorySize, GEMM_SMEM);
    cudaFuncSetAttribute(flash_f16,
                         cudaFuncAttributeMaxDynamicSharedMemorySize, FA_SMEM);

    // 0) convert inputs to fp16
    f32_to_f16_kernel<<<(T_TOK * HID / 4 + 255) / 256, 256>>>(hs, p_hs, T_TOK * HID / 4);
    f32_to_f16_kernel<<<(QKV_N * HID / 4 + 255) / 256, 256>>>(wqkv, p_wqkv, QKV_N * HID / 4);
    f32_to_f16_kernel<<<(HID * HID / 4 + 255) / 256, 256>>>(wdense, p_wd, HID * HID / 4);

    // 1) QKV projection (fp16 in, fp32 out)
    {
        dim3 grid(QKV_N / 128, T_TOK / 128);
        gemm_f16_nt<<<grid, 256, GEMM_SMEM>>>(p_hs, p_wqkv, p_qkv, T_TOK, QKV_N, HID);
    }
    // 2) RoPE + split (emits fp16 q*0.125*log2e, k, V^T)
    rope_split_kernel<<<T_TOK, 256>>>(p_qkv, cosb, sinb, p_q, p_k, p_vt);

    // 3) causal flash attention
    {
        dim3 grid(SEQ / 128, NHEAD, BATCH);
        flash_f16<<<grid, 256, FA_SMEM>>>(p_q, p_k, p_vt, p_attn);
    }
    // 4) dense projection (fp16 in, fp32 out)
    {
        dim3 grid(HID / 128, T_TOK / 128);
        gemm_f16_nt<<<grid, 256, GEMM_SMEM>>>(p_attn, p_wd, out, T_TOK, HID, HID);
    }
}